// round 16
// baseline (speedup 1.0000x reference)
#include <cuda_runtime.h>
#include <math.h>

#define BB 8
#define CC 128
#define HH 256
#define WW 256
#define NPIX (HH*WW)        // 65536
#define NPIX4 (NPIX/4)      // 16384
#define NOUT (BB*CC*NPIX)   // 67108864
#define OFF_ATTN ((size_t)NOUT)
#define OFF_W (OFF_ATTN + (size_t)BB*NPIX)
#define OFF_ALPHA (OFF_W + (size_t)BB*CC)
#define FNEG 3.402823466e38f
#define NTILE 128            // k1 tiles per batch plane

// ---------------------------------------------------------------------------
// Compile-time DWT position-weight table a[256].
// ---------------------------------------------------------------------------
struct WaTable {
    float v[256];
    constexpr WaTable() : v{} {
        const float declo[16] = {
            -0.00011747678400228192f, 0.0006754494059985568f, -0.0003917403729959771f,
            -0.00487035299301066f, 0.008746094047015655f, 0.013981027917015516f,
            -0.04408825393106472f, -0.01736930100202211f, 0.128747426620186f,
            0.00047248457399797254f, -0.2840155429624281f, -0.015829105256023893f,
            0.5853546836548691f, 0.6756307362980128f, 0.3128715909144659f,
            0.05441584224308161f };
        for (int j = 1; j <= 284; ++j) {
            int m = (j < 15) ? (14 - j) : ((j <= 270) ? (j - 15) : (526 - j));
            int klo = j - 1 - 268; if (klo < 0) klo = 0;
            int khi = j - 1;       if (khi > 15) khi = 15;
            if ((klo & 1) != ((j - 1) & 1)) klo++;
            float add = 0.f;
            for (int k = klo; k <= khi; k += 2) add += declo[15 - k];
            v[m] += add;
        }
    }
};
__constant__ WaTable c_wa;

__device__ float g_ypart[BB*NTILE*CC];     // per-tile DWT partials (512 KB)
__device__ float g_wch[BB*CC];             // channel gate w
__device__ float g_alpha;
__device__ float g_s[BB*2*2*NPIX];         // per-half (sum,max) planes, 8 MB

__device__ __forceinline__ float warp_sum(float v) {
    v += __shfl_xor_sync(0xffffffffu, v, 16);
    v += __shfl_xor_sync(0xffffffffu, v, 8);
    v += __shfl_xor_sync(0xffffffffu, v, 4);
    v += __shfl_xor_sync(0xffffffffu, v, 2);
    v += __shfl_xor_sync(0xffffffffu, v, 1);
    return v;
}

// ---------------------------------------------------------------------------
// K1: stats pass, block-unified channel walk, CHANNEL-SPLIT across blocks.
// grid 2048 (= BB * 128 tiles * 2 halves), block 128 (4 warps).
// Each block walks 64 CONSECUTIVE channels over one 128-float4 tile:
// per-block stream = 2 KB contiguous hop + 256 KB stride (the R8-proven
// shape), but 2x blocks -> ~55 warps/SM (occ ~82%), 2x in-flight bytes.
// No atomics anywhere. Per-pixel (sum,max) partials go to per-half planes;
// the conv combines halves during its tile load.
// ---------------------------------------------------------------------------
__global__ void __launch_bounds__(128) k1_reduce(const float* __restrict__ x) {
    __shared__ float sacc[4][64];
    int t = threadIdx.x;
    int warp = t >> 5, lane = t & 31;
    int blk = blockIdx.x;
    int b    = blk >> 8;                      // batch
    int half = (blk >> 7) & 1;                // channel half
    int tile = blk & 127;                     // tile in plane
    int p = tile * 128 + t;                   // float4 index in plane

    float wh = c_wa.v[p >> 6];
    int w0 = (p & 63) << 2;
    float4 wt = make_float4(c_wa.v[w0]*wh, c_wa.v[w0+1]*wh,
                            c_wa.v[w0+2]*wh, c_wa.v[w0+3]*wh);

    const float4* xp = (const float4*)x
                     + (size_t)(b * CC + half * 64) * NPIX4 + p;

    float4 psum = make_float4(0.f, 0.f, 0.f, 0.f);
    float4 pmax = make_float4(-FNEG, -FNEG, -FNEG, -FNEG);

    #pragma unroll 1
    for (int c0 = 0; c0 < 64; c0 += 8) {
        #pragma unroll
        for (int ci = 0; ci < 8; ++ci) {
            int c = c0 + ci;
            float4 v = __ldcs(xp + (size_t)c * NPIX4);
            psum.x += v.x; psum.y += v.y; psum.z += v.z; psum.w += v.w;
            pmax.x = fmaxf(pmax.x, v.x); pmax.y = fmaxf(pmax.y, v.y);
            pmax.z = fmaxf(pmax.z, v.z); pmax.w = fmaxf(pmax.w, v.w);
            float wsj = v.x * wt.x;
            wsj = fmaf(v.y, wt.y, wsj);
            wsj = fmaf(v.z, wt.z, wsj);
            wsj = fmaf(v.w, wt.w, wsj);
            wsj = warp_sum(wsj);
            if (lane == 0) sacc[warp][c] = wsj;
        }
        __syncthreads();                      // bound warp drift (lockstep)
    }

    // interleaved (sum,max) pairs into this half's plane
    float4* gs2 = (float4*)g_s + (size_t)(b*2 + half) * (2 * NPIX4) + 2 * p;
    gs2[0] = make_float4(psum.x, pmax.x, psum.y, pmax.y);
    gs2[1] = make_float4(psum.z, pmax.z, psum.w, pmax.w);

    // fold per-warp DWT partials: private slots, no atomics
    if (t < 64) {
        float r = sacc[0][t] + sacc[1][t] + sacc[2][t] + sacc[3][t];
        g_ypart[(b * NTILE + tile) * CC + half * 64 + t] = r;
    }
}

// ---------------------------------------------------------------------------
// K23: blocks [0,2048): 7x7 conv + sigmoid -> attn, 32x8 output tiles,
//      1 output/thread, float2-packed channels, dual accumulator chains.
//      Tile load combines the two k1 half-planes: avg=(sa+sb)/128,
//      max=max(ma,mb).
//      blocks [2048,2056): reduce g_ypart + FC chain -> w gate, alpha.
// ---------------------------------------------------------------------------
__global__ void __launch_bounds__(256) k23_mid(const float* __restrict__ cw,
                                               const float* __restrict__ fc1,
                                               const float* __restrict__ fc2,
                                               const float* __restrict__ weight,
                                               float* __restrict__ d_out) {
    int t = threadIdx.x;
    if (blockIdx.x < 2048) {
        // ---- conv ----
        __shared__ float2 wf2[49];
        __shared__ float2 tile2[14][40];
        int idx = blockIdx.x & 255;
        int b = blockIdx.x >> 8;
        int tx = t & 31, ty = t >> 5;
        if (t < 49) wf2[t] = make_float2(cw[t], cw[49 + t]);

        int gx0 = (idx & 7) * 32 - 3;
        int gy0 = (idx >> 3) * 8 - 3;
        const float2* sa = (const float2*)g_s + (size_t)(b*2    ) * NPIX;
        const float2* sb = (const float2*)g_s + (size_t)(b*2 + 1) * NPIX;

        const float inv = 1.f / 128.f;
        for (int i = t; i < 14*38; i += 256) {
            int r  = i / 38;
            int cl = i % 38;
            int gy = gy0 + r, gx = gx0 + cl;
            float2 v = make_float2(0.f, 0.f);
            if (gy >= 0 && gy < HH && gx >= 0 && gx < WW) {
                float2 va = sa[gy*WW + gx];
                float2 vb = sb[gy*WW + gx];
                v = make_float2((va.x + vb.x) * inv, fmaxf(va.y, vb.y));
            }
            tile2[r][cl] = v;
        }
        __syncthreads();

        float acc0 = 0.f, acc1 = 0.f;
        #pragma unroll
        for (int ky = 0; ky < 7; ++ky)
            #pragma unroll
            for (int kx = 0; kx < 7; ++kx) {
                float2 tv = tile2[ty+ky][tx+kx];
                float2 w2 = wf2[ky*7 + kx];
                acc0 = fmaf(tv.x, w2.x, acc0);
                acc1 = fmaf(tv.y, w2.y, acc1);
            }
        float acc = acc0 + acc1;

        int oy = (idx >> 3) * 8 + ty, ox = (idx & 7) * 32 + tx;
        d_out[OFF_ATTN + (size_t)b*NPIX + oy*WW + ox] = 1.f / (1.f + expf(-acc));
    } else {
        // ---- reduce partials + FC ----
        int b = blockIdx.x - 2048;
        __shared__ float yh[2][CC];
        __shared__ float y[CC];
        __shared__ float hsm[8];
        {
            int c = t & 127;
            int half = t >> 7;                // tiles 0-63 / 64-127
            const float* yp = g_ypart + (size_t)(b * NTILE + half * 64) * CC + c;
            float s = 0.f;
            #pragma unroll 8
            for (int tl = 0; tl < 64; ++tl) s += yp[tl * CC];
            yh[half][c] = s;
        }
        __syncthreads();
        if (t < CC)
            y[t] = (yh[0][t] + yh[1][t]) * (1.0f / (135.0f * 135.0f));
        __syncthreads();
        {
            int wj = t >> 5;      // warp 0..7 -> h[wj]
            int lane = t & 31;
            float4 fw = *(const float4*)(fc1 + wj*CC + lane*4);
            float part = fw.x*y[lane*4] + fw.y*y[lane*4+1]
                       + fw.z*y[lane*4+2] + fw.w*y[lane*4+3];
            float hv = warp_sum(part);
            if (lane == 0) hsm[wj] = fmaxf(hv, 0.f);
        }
        __syncthreads();
        if (t < CC) {
            float a = 0.f;
            #pragma unroll
            for (int j = 0; j < 8; ++j) a += fc2[t*8 + j] * hsm[j];
            float wv = 1.f / (1.f + expf(-a));
            g_wch[b*CC + t] = wv;
            d_out[OFF_W + b*CC + t] = wv;
        }
        if (b == 0 && t == 128) {
            float al = 1.f / (1.f + expf(-weight[0]));
            g_alpha = al;
            d_out[OFF_ALPHA] = al;
        }
    }
}

// ---------------------------------------------------------------------------
// K4: out = x * (alpha*attn + (1-alpha)*w). UNCHANGED (at LTS cap).
// ---------------------------------------------------------------------------
__global__ void __launch_bounds__(256) k4_out(const float* __restrict__ x,
                                              float* __restrict__ d_out) {
    int i0 = blockIdx.x * 1024 + threadIdx.x;
    const float4* x4 = (const float4*)x;
    const float4* a4 = (const float4*)(d_out + OFF_ATTN);
    float alpha = g_alpha;
    float om = 1.f - alpha;

    float4 v[4], at[4];
    float wv[4];
    #pragma unroll
    for (int u = 0; u < 4; ++u) {
        int i = i0 + u * 256;
        v[u] = __ldcs(&x4[i]);
    }
    #pragma unroll
    for (int u = 0; u < 4; ++u) {
        int i = i0 + u * 256;
        int b = i >> 21;
        int g = i & (NPIX4 - 1);
        at[u] = a4[(size_t)b * NPIX4 + g];
        wv[u] = g_wch[i >> 14];
    }
    #pragma unroll
    for (int u = 0; u < 4; ++u) {
        int i = i0 + u * 256;
        float base = om * wv[u];
        float4 o;
        o.x = v[u].x * fmaf(alpha, at[u].x, base);
        o.y = v[u].y * fmaf(alpha, at[u].y, base);
        o.z = v[u].z * fmaf(alpha, at[u].z, base);
        o.w = v[u].w * fmaf(alpha, at[u].w, base);
        __stcs(&((float4*)d_out)[i], o);
    }
}

extern "C" void kernel_launch(void* const* d_in, const int* in_sizes, int n_in,
                              void* d_out, int out_size) {
    const float* x    = (const float*)d_in[0];
    const float* cw   = (const float*)d_in[1];
    const float* fc1  = (const float*)d_in[2];
    const float* fc2  = (const float*)d_in[3];
    const float* wsc  = (const float*)d_in[4];
    float* out = (float*)d_out;

    k1_reduce<<<BB * NTILE * 2, 128>>>(x);
    k23_mid<<<2056, 256>>>(cw, fc1, fc2, wsc, out);
    k4_out<<<NOUT/4/1024, 256>>>(x, out);
}

// round 17
// speedup vs baseline: 1.0902x; 1.0902x over previous
#include <cuda_runtime.h>
#include <math.h>

#define BB 8
#define CC 128
#define HH 256
#define WW 256
#define NPIX (HH*WW)        // 65536
#define NPIX4 (NPIX/4)      // 16384
#define NOUT (BB*CC*NPIX)   // 67108864
#define OFF_ATTN ((size_t)NOUT)
#define OFF_W (OFF_ATTN + (size_t)BB*NPIX)
#define OFF_ALPHA (OFF_W + (size_t)BB*CC)
#define FNEG 3.402823466e38f
#define NTILE 128            // k1 tiles per batch plane

// ---------------------------------------------------------------------------
// Compile-time DWT position-weight table a[256].
// ---------------------------------------------------------------------------
struct WaTable {
    float v[256];
    constexpr WaTable() : v{} {
        const float declo[16] = {
            -0.00011747678400228192f, 0.0006754494059985568f, -0.0003917403729959771f,
            -0.00487035299301066f, 0.008746094047015655f, 0.013981027917015516f,
            -0.04408825393106472f, -0.01736930100202211f, 0.128747426620186f,
            0.00047248457399797254f, -0.2840155429624281f, -0.015829105256023893f,
            0.5853546836548691f, 0.6756307362980128f, 0.3128715909144659f,
            0.05441584224308161f };
        for (int j = 1; j <= 284; ++j) {
            int m = (j < 15) ? (14 - j) : ((j <= 270) ? (j - 15) : (526 - j));
            int klo = j - 1 - 268; if (klo < 0) klo = 0;
            int khi = j - 1;       if (khi > 15) khi = 15;
            if ((klo & 1) != ((j - 1) & 1)) klo++;
            float add = 0.f;
            for (int k = klo; k <= khi; k += 2) add += declo[15 - k];
            v[m] += add;
        }
    }
};
__constant__ WaTable c_wa;

__device__ float g_ypart[BB*NTILE*CC];     // per-tile DWT partials (512 KB)
__device__ float g_wch[BB*CC];             // channel gate w
__device__ float g_alpha;
__device__ float g_s[BB*2*NPIX];           // interleaved (avg,max) per pixel

__device__ __forceinline__ float warp_sum(float v) {
    v += __shfl_xor_sync(0xffffffffu, v, 16);
    v += __shfl_xor_sync(0xffffffffu, v, 8);
    v += __shfl_xor_sync(0xffffffffu, v, 4);
    v += __shfl_xor_sync(0xffffffffu, v, 2);
    v += __shfl_xor_sync(0xffffffffu, v, 1);
    return v;
}

// ---------------------------------------------------------------------------
// K1: stats pass, block-unified channel walk (R8/R14-proven, UNTOUCHED).
// grid 1024 (= BB * 128 tiles), block 128 (4 warps). One block = one
// coherent DRAM stream: 2 KB contiguous hop, 256 KB channel stride.
// 1024 streams is the empirically-optimal count (2048 and per-warp splits
// both regress). g_s stores (avg,max) interleaved per pixel for the conv.
// ---------------------------------------------------------------------------
__global__ void __launch_bounds__(128) k1_reduce(const float* __restrict__ x) {
    __shared__ float sacc[4][CC];
    int t = threadIdx.x;
    int warp = t >> 5, lane = t & 31;
    int b = blockIdx.x >> 7;                  // batch
    int tile = blockIdx.x & 127;              // 128 tiles of 128 float4
    int p = tile * 128 + t;                   // float4 index in plane

    float wh = c_wa.v[p >> 6];
    int w0 = (p & 63) << 2;
    float4 wt = make_float4(c_wa.v[w0]*wh, c_wa.v[w0+1]*wh,
                            c_wa.v[w0+2]*wh, c_wa.v[w0+3]*wh);

    const float4* xp = (const float4*)x + (size_t)(b * CC) * NPIX4 + p;

    float4 psum = make_float4(0.f, 0.f, 0.f, 0.f);
    float4 pmax = make_float4(-FNEG, -FNEG, -FNEG, -FNEG);

    #pragma unroll 1
    for (int c0 = 0; c0 < CC; c0 += 8) {
        #pragma unroll
        for (int ci = 0; ci < 8; ++ci) {
            int c = c0 + ci;
            float4 v = __ldcs(xp + (size_t)c * NPIX4);
            psum.x += v.x; psum.y += v.y; psum.z += v.z; psum.w += v.w;
            pmax.x = fmaxf(pmax.x, v.x); pmax.y = fmaxf(pmax.y, v.y);
            pmax.z = fmaxf(pmax.z, v.z); pmax.w = fmaxf(pmax.w, v.w);
            float wsj = v.x * wt.x;
            wsj = fmaf(v.y, wt.y, wsj);
            wsj = fmaf(v.z, wt.z, wsj);
            wsj = fmaf(v.w, wt.w, wsj);
            wsj = warp_sum(wsj);
            if (lane == 0) sacc[warp][c] = wsj;
        }
        __syncthreads();                      // bound warp drift (lockstep)
    }

    const float inv = 1.f / 128.f;
    float4* gs2 = (float4*)g_s + (size_t)b * (2 * NPIX4) + 2 * p;
    gs2[0] = make_float4(psum.x*inv, pmax.x, psum.y*inv, pmax.y);
    gs2[1] = make_float4(psum.z*inv, pmax.z, psum.w*inv, pmax.w);

    float r = sacc[0][t] + sacc[1][t] + sacc[2][t] + sacc[3][t];
    g_ypart[(b * NTILE + tile) * CC + t] = r;
}

// ---------------------------------------------------------------------------
// K23: blocks [0,1024): 7x7 conv + sigmoid -> attn, 32x16 output tiles,
//      2 adjacent-y outputs/thread: the shared 8-row window needs only
//      56 tile-LDS.64 per 2 outputs (vs 98), and 4 interleaved accumulator
//      chains (2 outputs x 2 channels) double FMA ILP.
//      blocks [1024,1032): reduce g_ypart + FC chain -> w gate, alpha.
// ---------------------------------------------------------------------------
__global__ void __launch_bounds__(256) k23_mid(const float* __restrict__ cw,
                                               const float* __restrict__ fc1,
                                               const float* __restrict__ fc2,
                                               const float* __restrict__ weight,
                                               float* __restrict__ d_out) {
    int t = threadIdx.x;
    if (blockIdx.x < 1024) {
        // ---- conv: 32x16 tile, halo 22x38, 2 y-outputs per thread ----
        __shared__ float2 wf2[49];
        __shared__ float2 tile2[22][40];
        int idx = blockIdx.x & 127;           // 8 x-tiles x 16 y-tiles
        int b = blockIdx.x >> 7;
        int tx = t & 31, ty = t >> 5;         // (32,8)
        if (t < 49) wf2[t] = make_float2(cw[t], cw[49 + t]);

        int gx0 = (idx & 7) * 32 - 3;
        int gy0 = (idx >> 3) * 16 - 3;
        const float2* s2 = (const float2*)g_s + (size_t)b * NPIX;

        for (int i = t; i < 22*38; i += 256) {
            int r  = i / 38;
            int cl = i % 38;
            int gy = gy0 + r, gx = gx0 + cl;
            float2 v = make_float2(0.f, 0.f);
            if (gy >= 0 && gy < HH && gx >= 0 && gx < WW)
                v = s2[gy*WW + gx];
            tile2[r][cl] = v;
        }
        __syncthreads();

        float a0x = 0.f, a0y = 0.f, a1x = 0.f, a1y = 0.f;
        #pragma unroll
        for (int ky = 0; ky < 8; ++ky) {
            int row = 2*ty + ky;
            #pragma unroll
            for (int kx = 0; kx < 7; ++kx) {
                float2 tv = tile2[row][tx+kx];
                if (ky < 7) {
                    float2 w = wf2[ky*7 + kx];
                    a0x = fmaf(tv.x, w.x, a0x);
                    a0y = fmaf(tv.y, w.y, a0y);
                }
                if (ky >= 1) {
                    float2 w = wf2[(ky-1)*7 + kx];
                    a1x = fmaf(tv.x, w.x, a1x);
                    a1y = fmaf(tv.y, w.y, a1y);
                }
            }
        }

        int oy0 = (idx >> 3) * 16 + 2*ty;
        int ox  = (idx & 7) * 32 + tx;
        float* oattn = d_out + OFF_ATTN + (size_t)b*NPIX;
        oattn[ oy0     *WW + ox] = 1.f / (1.f + expf(-(a0x + a0y)));
        oattn[(oy0 + 1)*WW + ox] = 1.f / (1.f + expf(-(a1x + a1y)));
    } else {
        // ---- reduce partials + FC ----
        int b = blockIdx.x - 1024;
        __shared__ float yh[2][CC];
        __shared__ float y[CC];
        __shared__ float hsm[8];
        {
            int c = t & 127;
            int half = t >> 7;                // tiles 0-63 / 64-127
            const float* yp = g_ypart + (size_t)(b * NTILE + half * 64) * CC + c;
            float s = 0.f;
            #pragma unroll 8
            for (int tl = 0; tl < 64; ++tl) s += yp[tl * CC];
            yh[half][c] = s;
        }
        __syncthreads();
        if (t < CC)
            y[t] = (yh[0][t] + yh[1][t]) * (1.0f / (135.0f * 135.0f));
        __syncthreads();
        {
            int wj = t >> 5;      // warp 0..7 -> h[wj]
            int lane = t & 31;
            float4 fw = *(const float4*)(fc1 + wj*CC + lane*4);
            float part = fw.x*y[lane*4] + fw.y*y[lane*4+1]
                       + fw.z*y[lane*4+2] + fw.w*y[lane*4+3];
            float hv = warp_sum(part);
            if (lane == 0) hsm[wj] = fmaxf(hv, 0.f);
        }
        __syncthreads();
        if (t < CC) {
            float a = 0.f;
            #pragma unroll
            for (int j = 0; j < 8; ++j) a += fc2[t*8 + j] * hsm[j];
            float wv = 1.f / (1.f + expf(-a));
            g_wch[b*CC + t] = wv;
            d_out[OFF_W + b*CC + t] = wv;
        }
        if (b == 0 && t == 128) {
            float al = 1.f / (1.f + expf(-weight[0]));
            g_alpha = al;
            d_out[OFF_ALPHA] = al;
        }
    }
}

// ---------------------------------------------------------------------------
// K4: out = x * (alpha*attn + (1-alpha)*w). UNCHANGED (at DRAM cap).
// ---------------------------------------------------------------------------
__global__ void __launch_bounds__(256) k4_out(const float* __restrict__ x,
                                              float* __restrict__ d_out) {
    int i0 = blockIdx.x * 1024 + threadIdx.x;
    const float4* x4 = (const float4*)x;
    const float4* a4 = (const float4*)(d_out + OFF_ATTN);
    float alpha = g_alpha;
    float om = 1.f - alpha;

    float4 v[4], at[4];
    float wv[4];
    #pragma unroll
    for (int u = 0; u < 4; ++u) {
        int i = i0 + u * 256;
        v[u] = __ldcs(&x4[i]);
    }
    #pragma unroll
    for (int u = 0; u < 4; ++u) {
        int i = i0 + u * 256;
        int b = i >> 21;
        int g = i & (NPIX4 - 1);
        at[u] = a4[(size_t)b * NPIX4 + g];
        wv[u] = g_wch[i >> 14];
    }
    #pragma unroll
    for (int u = 0; u < 4; ++u) {
        int i = i0 + u * 256;
        float base = om * wv[u];
        float4 o;
        o.x = v[u].x * fmaf(alpha, at[u].x, base);
        o.y = v[u].y * fmaf(alpha, at[u].y, base);
        o.z = v[u].z * fmaf(alpha, at[u].z, base);
        o.w = v[u].w * fmaf(alpha, at[u].w, base);
        __stcs(&((float4*)d_out)[i], o);
    }
}

extern "C" void kernel_launch(void* const* d_in, const int* in_sizes, int n_in,
                              void* d_out, int out_size) {
    const float* x    = (const float*)d_in[0];
    const float* cw   = (const float*)d_in[1];
    const float* fc1  = (const float*)d_in[2];
    const float* fc2  = (const float*)d_in[3];
    const float* wsc  = (const float*)d_in[4];
    float* out = (float*)d_out;

    k1_reduce<<<BB * NTILE, 128>>>(x);
    k23_mid<<<1032, 256>>>(cw, fc1, fc2, wsc, out);
    k4_out<<<NOUT/4/1024, 256>>>(x, out);
}